// round 6
// baseline (speedup 1.0000x reference)
#include <cuda_runtime.h>
#include <cstddef>

#define NEGF (-10000.0f)
constexpr int S_LEN = 1024;
constexpr int NLAB  = 49;
constexpr int L     = 51;   // start = 49, end = 50

__device__ __forceinline__ unsigned long long pk2(float a, float b) {
    unsigned long long r;
    asm("mov.b64 %0, {%1, %2};" : "=l"(r) : "f"(a), "f"(b));
    return r;
}
__device__ __forceinline__ void upk2(unsigned long long v, float& a, float& b) {
    asm("mov.b64 {%0, %1}, %2;" : "=f"(a), "=f"(b) : "l"(v));
}

// 49-term dot (k = 0..48, plus zeroed k=49) of q (shared, 13 x ulonglong2)
// with 25 packed eT pairs, 4 accumulator chains.
#define DOT49(EARR, OUT)                                                        \
    do {                                                                        \
        unsigned long long c0 = 0ull, c1 = 0ull, c2 = 0ull, c3 = 0ull;          \
        _Pragma("unroll")                                                       \
        for (int m = 0; m < 6; m++) {                                           \
            ulonglong2 qa = qp[2 * m], qb = qp[2 * m + 1];                      \
            asm("fma.rn.f32x2 %0, %1, %2, %0;" : "+l"(c0) : "l"(qa.x), "l"(EARR[4*m]));   \
            asm("fma.rn.f32x2 %0, %1, %2, %0;" : "+l"(c1) : "l"(qa.y), "l"(EARR[4*m+1])); \
            asm("fma.rn.f32x2 %0, %1, %2, %0;" : "+l"(c2) : "l"(qb.x), "l"(EARR[4*m+2])); \
            asm("fma.rn.f32x2 %0, %1, %2, %0;" : "+l"(c3) : "l"(qb.y), "l"(EARR[4*m+3])); \
        }                                                                       \
        {   /* pack 24 = floats 48,49 (q[49]=0, eT hi half = 0) */              \
            ulonglong2 qa = qp[12];                                             \
            asm("fma.rn.f32x2 %0, %1, %2, %0;" : "+l"(c0) : "l"(qa.x), "l"(EARR[24]));    \
        }                                                                       \
        unsigned long long s01, s23, sall;                                      \
        asm("add.rn.f32x2 %0, %1, %2;" : "=l"(s01) : "l"(c0), "l"(c1));         \
        asm("add.rn.f32x2 %0, %1, %2;" : "=l"(s23) : "l"(c2), "l"(c3));         \
        asm("add.rn.f32x2 %0, %1, %2;" : "=l"(sall) : "l"(s01), "l"(s23));      \
        float z0, z1;                                                           \
        upk2(sall, z0, z1);                                                     \
        OUT = z0 + z1;                                                          \
    } while (0)

__global__ __launch_bounds__(64) void crf_fwd_kernel(
    const float* __restrict__ logits,   // [B, S, NL]
    const float* __restrict__ trans,    // [L, L]
    const int*   __restrict__ labels,   // [B, S]
    const int*   __restrict__ lens,     // [B]
    float*       __restrict__ out)      // [B]
{
    __shared__ __align__(16) float qsh[2][56];   // q double buffer; slots 49..55 = 0
    __shared__ float sc_sh[4];                   // lag-2 pow2 scale ring
    __shared__ float norm_sh;
    __shared__ int   eacc_sh;
    __shared__ float red[64];

    const int b   = blockIdx.x;
    const int tid = threadIdx.x;           // thread i owns state i (i<49); tid 49 -> end row
    const int len = lens[b];

    const bool hasState = tid < NLAB;      // writes q
    const int  srow = hasState ? tid : (tid == 49 ? 50 : 0);
    const bool hasRow = (tid < NLAB) || (tid == 49);

    // ---- per-thread exp(T[srow, k]) for k = 0..48, packed as 25 f32x2 ----
    unsigned long long eT[25];
    {
        const float* r = trans + srow * L;
        #pragma unroll
        for (int q = 0; q < 24; q++) {
            float a = hasRow ? __expf(r[2 * q])     : 0.0f;
            float c = hasRow ? __expf(r[2 * q + 1]) : 0.0f;
            eT[q] = pk2(a, c);
        }
        eT[24] = pk2(hasRow ? __expf(r[48]) : 0.0f, 0.0f);
    }

    // ---- init shared ----
    if (tid < 56) { qsh[0][tid] = 0.0f; qsh[1][tid] = 0.0f; }
    if (tid < 4)  sc_sh[tid] = 1.0f;

    // ---- q1[j] = exp(lg0[j]) * exp(T[j, start=49]) ----
    const float* lp = logits + (size_t)b * S_LEN * NLAB;
    const int ci = hasState ? tid : 0;
    {
        float lg0 = __ldg(lp + ci);
        if (hasState)
            qsh[1][tid] = __expf(lg0) * __expf(__ldg(trans + tid * L + 49));
    }

    // prefetch ring for t = 1..8
    float rl[8];
    #pragma unroll
    for (int j = 0; j < 8; j++)
        rl[j] = __ldg(lp + (size_t)(1 + j) * NLAB + ci);

    // thread 0's normalizer bookkeeping (exponents of committed scales)
    int Eacc = 0;      // sum of applied scale exponents
    int p0 = 0;        // exponent of scale applied at current step t
    int p1 = 0;        // exponent of scale for step t+1 (already in ring)
    __syncthreads();

    for (int tb = 1; tb < len; tb += 8) {
        float vl[8];
        #pragma unroll
        for (int j = 0; j < 8; j++) vl[j] = __expf(rl[j]);

        #pragma unroll
        for (int j = 0; j < 8; j++) {
            const int t = tb + j;
            if (t >= len) break;
            const int par = t & 1;

            float sc = sc_sh[t & 3];      // = 2^{p0}; written at t-2
            float u  = vl[j] * sc;

            if (t + 8 < S_LEN)
                rl[j] = __ldg(lp + (size_t)(t + 8) * NLAB + ci);

            const ulonglong2* qp = reinterpret_cast<const ulonglong2*>(qsh[par]);
            float S;
            DOT49(eT, S);

            if (tid == 0) {
                // self-consistent lag-2: cancel predicted exponent of q_{t+2}
                int E  = (__float_as_int(S) >> 23) - 127;   // E(S_t), S > 0
                int p2 = -(E + p0 + p1);
                p2 = p2 < -100 ? -100 : (p2 > 100 ? 100 : p2);
                sc_sh[(t + 2) & 3] = __int_as_float((p2 + 127) << 23);
                Eacc += p0;
                p0 = p1; p1 = p2;
            }

            if (hasState) qsh[par ^ 1][tid] = S * u;
            __syncthreads();
        }
    }

    // ---- norm = log(Send) - Eacc*ln2 over final q (buffer len&1) ----
    if (tid == 0) eacc_sh = Eacc;
    __syncthreads();
    {
        const ulonglong2* qp = reinterpret_cast<const ulonglong2*>(qsh[len & 1]);
        float Send;
        DOT49(eT, Send);
        if (tid == 49)
            norm_sh = (float)((double)__logf(Send) -
                              (double)eacc_sh * 0.6931471805599453);
    }

    // ---- gold = unary + binary (parallel gather) ----
    const int* labp = labels + (size_t)b * S_LEN;
    float acc = 0.0f;
    #pragma unroll 4
    for (int t = tid; t < len; t += 64) {
        int lab = labp[t];
        acc += __ldg(lp + (size_t)t * NLAB + lab);
        int prev = t ? labp[t - 1] : (L - 2);
        acc += __ldg(trans + lab * L + prev);
    }
    if (tid == 0) acc += __ldg(trans + (L - 1) * L + labp[len - 1]);
    red[tid] = acc;
    __syncthreads();

    if (tid < 32) {
        float v = red[tid] + red[tid + 32];
        #pragma unroll
        for (int o = 16; o; o >>= 1) v += __shfl_down_sync(0xffffffffu, v, o);
        if (tid == 0) out[b] = v - norm_sh;
    }
}

extern "C" void kernel_launch(void* const* d_in, const int* in_sizes, int n_in,
                              void* d_out, int out_size)
{
    const float* logits = (const float*)d_in[0];
    const float* trans  = (const float*)d_in[1];
    const int*   labels = (const int*)d_in[2];
    const int*   lens   = (const int*)d_in[3];
    const int B = in_sizes[3];
    crf_fwd_kernel<<<B, 64>>>(logits, trans, labels, lens, (float*)d_out);
}

// round 7
// speedup vs baseline: 1.1984x; 1.1984x over previous
#include <cuda_runtime.h>
#include <cstddef>

#define NEGF (-10000.0f)
constexpr int S_LEN = 1024;
constexpr int NLAB  = 49;
constexpr int L     = 51;   // start = 49, end = 50

__device__ __forceinline__ unsigned long long pk2(float a, float b) {
    unsigned long long r;
    asm("mov.b64 %0, {%1, %2};" : "=l"(r) : "f"(a), "f"(b));
    return r;
}
__device__ __forceinline__ void upk2(unsigned long long v, float& a, float& b) {
    asm("mov.b64 {%0, %1}, %2;" : "=f"(a), "=f"(b) : "l"(v));
}

// 25 packed FMA2 over k = 0..49 (q[49] == 0 kills the junk half of pack 24),
// reading q pairs from the register array qq[13]. 4 accumulator chains.
#define DOT25(EARR, OUT)                                                          \
    do {                                                                          \
        unsigned long long c0 = 0ull, c1 = 0ull, c2 = 0ull, c3 = 0ull;            \
        _Pragma("unroll")                                                         \
        for (int m = 0; m < 6; m++) {                                             \
            asm("fma.rn.f32x2 %0, %1, %2, %0;" : "+l"(c0) : "l"(qq[2*m].x),   "l"(EARR[4*m]));   \
            asm("fma.rn.f32x2 %0, %1, %2, %0;" : "+l"(c1) : "l"(qq[2*m].y),   "l"(EARR[4*m+1])); \
            asm("fma.rn.f32x2 %0, %1, %2, %0;" : "+l"(c2) : "l"(qq[2*m+1].x), "l"(EARR[4*m+2])); \
            asm("fma.rn.f32x2 %0, %1, %2, %0;" : "+l"(c3) : "l"(qq[2*m+1].y), "l"(EARR[4*m+3])); \
        }                                                                         \
        asm("fma.rn.f32x2 %0, %1, %2, %0;" : "+l"(c0) : "l"(qq[12].x), "l"(EARR[24]));           \
        unsigned long long s01, s23, sall;                                        \
        asm("add.rn.f32x2 %0, %1, %2;" : "=l"(s01) : "l"(c0), "l"(c1));           \
        asm("add.rn.f32x2 %0, %1, %2;" : "=l"(s23) : "l"(c2), "l"(c3));           \
        asm("add.rn.f32x2 %0, %1, %2;" : "=l"(sall) : "l"(s01), "l"(s23));        \
        float z0, z1;                                                             \
        upk2(sall, z0, z1);                                                       \
        OUT = z0 + z1;                                                            \
    } while (0)

__global__ __launch_bounds__(32) void crf_fwd_kernel(
    const float* __restrict__ logits,   // [B, S, NL]
    const float* __restrict__ trans,    // [L, L]
    const int*   __restrict__ labels,   // [B, S]
    const int*   __restrict__ lens,     // [B]
    float*       __restrict__ out)      // [B]
{
    __shared__ __align__(16) float qsh[2][56];   // slots 49..55 stay 0
    __shared__ float norm_sh;

    const int b    = blockIdx.x;
    const int lane = threadIdx.x;
    const int len  = lens[b];

    // row ownership: lo = state lane (0..31); hi = state lane+32 (lanes 0..16),
    // lane 17 hi = end row 50 (used only for the final norm), others dead.
    const bool hasHiQ  = lane < 17;                 // writes q[32+lane]
    const int  hiRow   = hasHiQ ? (lane + 32) : (lane == 17 ? 50 : 0);
    const bool hasHiRow = lane <= 17;

    // ---- exp(T[row, k]) for k = 0..49, packed as 25 f32x2 ----
    unsigned long long eLo[25], eHi[25];
    {
        const float* rlo = trans + lane * L;
        const float* rhi = trans + hiRow * L;
        #pragma unroll
        for (int p = 0; p < 25; p++) {
            eLo[p] = pk2(__expf(rlo[2 * p]), __expf(rlo[2 * p + 1]));
            float d = 0.0f, e = 0.0f;
            if (hasHiRow) { d = __expf(rhi[2 * p]); e = __expf(rhi[2 * p + 1]); }
            eHi[p] = pk2(d, e);
        }
    }

    // ---- init shared; q1[j] = exp(lg0[j]) * exp(T[j, start=49]) ----
    for (int i = lane; i < 56; i += 32) { qsh[0][i] = 0.0f; qsh[1][i] = 0.0f; }
    __syncwarp();
    const float* lp = logits + (size_t)b * S_LEN * NLAB;
    {
        qsh[1][lane] = __expf(__ldg(lp + lane)) * __expf(__ldg(trans + lane * L + 49));
        if (hasHiQ)
            qsh[1][lane + 32] = __expf(__ldg(lp + lane + 32)) *
                                __expf(__ldg(trans + (lane + 32) * L + 49));
    }

    // ---- prefetch ring for t = 1..8 ----
    const int ciHi = hasHiQ ? (lane + 32) : 0;
    float rl[8], rh[8];
    #pragma unroll
    for (int j = 0; j < 8; j++) {
        rl[j] = __ldg(lp + (size_t)(1 + j) * NLAB + lane);
        rh[j] = hasHiQ ? __ldg(lp + (size_t)(1 + j) * NLAB + ciHi) : NEGF;
    }

    int Eacc = 0;   // uniform across lanes: sum of applied scale exponents
    __syncwarp();

    for (int tb = 1; tb < len; tb += 8) {
        float vl[8], vh[8];
        #pragma unroll
        for (int j = 0; j < 8; j++) {
            vl[j] = __expf(rl[j]);
            vh[j] = hasHiQ ? __expf(rh[j]) : 0.0f;
        }

        #pragma unroll
        for (int j = 0; j < 8; j++) {
            const int t = tb + j;
            if (t >= len) break;
            const int par = t & 1;

            // q_t -> registers (broadcast LDS.128 x13)
            ulonglong2 qq[13];
            const ulonglong2* qp = reinterpret_cast<const ulonglong2*>(qsh[par]);
            #pragma unroll
            for (int i = 0; i < 13; i++) qq[i] = qp[i];

            // lag-0 lane-uniform pow2 rescale from q_t[0] (already in all lanes)
            float q0, q0b;
            upk2(qq[0].x, q0, q0b);
            int be = __float_as_int(q0) >> 23;      // q0 > 0
            Eacc += be - 127;
            float sc = __int_as_float((254 - be) << 23);
            float ulo = vl[j] * sc;
            float uhi = vh[j] * sc;

            if (t + 8 < S_LEN) {
                rl[j] = __ldg(lp + (size_t)(t + 8) * NLAB + lane);
                if (hasHiQ) rh[j] = __ldg(lp + (size_t)(t + 8) * NLAB + ciHi);
            }

            float Slo, Shi;
            DOT25(eLo, Slo);
            DOT25(eHi, Shi);

            qsh[par ^ 1][lane] = Slo * ulo;
            if (hasHiQ) qsh[par ^ 1][lane + 32] = Shi * uhi;
            __syncwarp();
        }
    }

    // ---- norm = log(Send) + Eacc*ln2; Send = lane 17's hi dot over q_len ----
    {
        ulonglong2 qq[13];
        const ulonglong2* qp = reinterpret_cast<const ulonglong2*>(qsh[len & 1]);
        #pragma unroll
        for (int i = 0; i < 13; i++) qq[i] = qp[i];
        float Send;
        DOT25(eHi, Send);
        if (lane == 17)
            norm_sh = (float)((double)__logf(Send) +
                              (double)Eacc * 0.6931471805599453);
    }

    // ---- gold = unary + binary (parallel gather) ----
    const int* labp = labels + (size_t)b * S_LEN;
    float acc = 0.0f;
    #pragma unroll 4
    for (int t = lane; t < len; t += 32) {
        int lab = labp[t];
        acc += __ldg(lp + (size_t)t * NLAB + lab);
        int prev = t ? labp[t - 1] : (L - 2);
        acc += __ldg(trans + lab * L + prev);
    }
    if (lane == 0) acc += __ldg(trans + (L - 1) * L + labp[len - 1]);
    #pragma unroll
    for (int o = 16; o; o >>= 1) acc += __shfl_down_sync(0xffffffffu, acc, o);
    __syncwarp();

    if (lane == 0) out[b] = acc - norm_sh;
}

extern "C" void kernel_launch(void* const* d_in, const int* in_sizes, int n_in,
                              void* d_out, int out_size)
{
    const float* logits = (const float*)d_in[0];
    const float* trans  = (const float*)d_in[1];
    const int*   labels = (const int*)d_in[2];
    const int*   lens   = (const int*)d_in[3];
    const int B = in_sizes[3];
    crf_fwd_kernel<<<B, 32>>>(logits, trans, labels, lens, (float*)d_out);
}